// round 11
// baseline (speedup 1.0000x reference)
#include <cuda_runtime.h>
#include <cuda_bf16.h>
#include <math.h>

// Problem constants
#define BATCH 8
#define MDIM 256
#define NDIM 256
#define DDIM 512
#define NDIAG 511            // M + N - 1
#define INFV 100000000.0f    // matches reference _INF
#define GAMMA_MIN 0.0001f

#define UNRP 4               // pair-unroll / prefetch depth (pairs)

// ---------------------------------------------------------------------------
// Scratch (static device globals; no allocation)
// layout: diag-major  [b][d][i]  with i = row index (global m), d = m + n
// ---------------------------------------------------------------------------
__device__ float  g_rx[BATCH * MDIM];                 // 1/||x_m||
__device__ float  g_ry[BATCH * NDIM];                 // 1/||y_n||
__device__ float  g_cost[BATCH * NDIAG * MDIM];       // cost, diag-major
__device__ float  g_R[BATCH * NDIAG * MDIM];          // R (interior), diag-major
__device__ float  g_S[BATCH * NDIAG * MDIM];          // softmin value (= R - cost)
__device__ float4 g_W[BATCH * NDIAG * MDIM];          // (wd, wn, wr, 0) per cell
__device__ float  g_E[BATCH * NDIAG * MDIM];          // alignment, diag-major

__device__ __forceinline__ float clamp50(float v)
{
    return fminf(fmaxf(v, -50.0f), 50.0f);
}

__device__ __forceinline__ float ex2_(float x)       // MUFU.EX2
{
    float r;
    asm("ex2.approx.f32 %0, %1;" : "=f"(r) : "f"(x));
    return r;
}
__device__ __forceinline__ float lg2_(float x)       // MUFU.LG2
{
    float r;
    asm("lg2.approx.f32 %0, %1;" : "=f"(r) : "f"(x));
    return r;
}

// softmin_3 via exp2/log2 with folded constants:
//   Sv = mn - gl * log2( sum exp2((mn - v) * ig2) )
__device__ __forceinline__ float softmin3(float a, float b, float c,
                                          float ig2, float gl)
{
    float mn = fminf(a, fminf(b, c));
    float s  = ex2_((mn - a) * ig2)
             + ex2_((mn - b) * ig2)
             + ex2_((mn - c) * ig2);
    return mn - gl * lg2_(s);
}

// ---------------------------------------------------------------------------
// Kernel 1: inverse row norms for x and y.  One warp per row.
// ---------------------------------------------------------------------------
__global__ __launch_bounds__(256) void norms_kernel(const float* __restrict__ x,
                                                    const float* __restrict__ y)
{
    int warp = threadIdx.x >> 5;
    int lane = threadIdx.x & 31;
    int row  = blockIdx.x * 8 + warp;          // 512 blocks * 8 warps = 4096 rows

    const float* base;
    float* out;
    if (row < BATCH * MDIM) {
        base = x + (size_t)row * DDIM;
        out  = g_rx + row;
    } else {
        int r = row - BATCH * MDIM;
        base = y + (size_t)r * DDIM;
        out  = g_ry + r;
    }

    const float4* b4 = reinterpret_cast<const float4*>(base);
    float s = 0.0f;
#pragma unroll
    for (int t = 0; t < 4; ++t) {
        float4 v = b4[lane + 32 * t];          // 128 float4 per row
        s += v.x * v.x + v.y * v.y + v.z * v.z + v.w * v.w;
    }
#pragma unroll
    for (int o = 16; o; o >>= 1) s += __shfl_xor_sync(0xFFFFFFFFu, s, o);

    if (lane == 0) {
        float n = sqrtf(s);
        n = fmaxf(n, 1e-8f);
        *out = 1.0f / n;
    }
}

// ---------------------------------------------------------------------------
// Kernel 2: cost = 1 - (x.y) * rx * ry, written DIAG-MAJOR.
// Tiled SGEMM: 64x64 tile per block, BK=16, 256 threads, 4x4 microtile.
// ---------------------------------------------------------------------------
#define BM 64
#define BN 64
#define BK 16

__global__ __launch_bounds__(256) void cost_kernel(const float* __restrict__ x,
                                                   const float* __restrict__ y)
{
    __shared__ float Xs[BK][BM + 1];
    __shared__ float Ys[BK][BN + 1];

    int b  = blockIdx.z;
    int m0 = blockIdx.y * BM;
    int n0 = blockIdx.x * BN;
    int tx = threadIdx.x;      // 0..15
    int ty = threadIdx.y;      // 0..15
    int tid = ty * 16 + tx;

    const float* xb = x + ((size_t)b * MDIM + m0) * DDIM;
    const float* yb = y + ((size_t)b * NDIM + n0) * DDIM;

    float acc[4][4];
#pragma unroll
    for (int r = 0; r < 4; ++r)
#pragma unroll
        for (int c = 0; c < 4; ++c) acc[r][c] = 0.0f;

    int kk = tid & 15;
    int rr = tid >> 4;

    for (int k0 = 0; k0 < DDIM; k0 += BK) {
#pragma unroll
        for (int r = 0; r < 4; ++r) {
            Xs[kk][rr + r * 16] = xb[(size_t)(rr + r * 16) * DDIM + k0 + kk];
            Ys[kk][rr + r * 16] = yb[(size_t)(rr + r * 16) * DDIM + k0 + kk];
        }
        __syncthreads();
#pragma unroll
        for (int k = 0; k < BK; ++k) {
            float a[4], bv[4];
#pragma unroll
            for (int r = 0; r < 4; ++r) a[r]  = Xs[k][ty * 4 + r];
#pragma unroll
            for (int c = 0; c < 4; ++c) bv[c] = Ys[k][tx * 4 + c];
#pragma unroll
            for (int r = 0; r < 4; ++r)
#pragma unroll
                for (int c = 0; c < 4; ++c) acc[r][c] += a[r] * bv[c];
        }
        __syncthreads();
    }

    float* costb = g_cost + (size_t)b * NDIAG * MDIM;
#pragma unroll
    for (int r = 0; r < 4; ++r) {
        int row = m0 + ty * 4 + r;
        float rx = g_rx[b * MDIM + row];
#pragma unroll
        for (int c = 0; c < 4; ++c) {
            int col = n0 + tx * 4 + c;
            float ry = g_ry[b * NDIM + col];
            float v = 1.0f - acc[r][c] * rx * ry;
            costb[(size_t)(row + col) * MDIM + row] = v;   // diag-major
        }
    }
}

// ---------------------------------------------------------------------------
// Kernel 3: forward soft-DTW wavefront, TWO diagonals per barrier.
// Pair p handles dA = 2p, dB = 2p+1.  After the barrier, smem holds diags
// dA-1, dA-2.  Each thread computes:
//   (1) its own cell (i, dA)          [from smem]
//   (2) a redundant halo cell (i-1,dA) [from smem, independent -> ILP]
//   (3) its cell (i, dB) from registers only:
//         a1 = R(dA-1, i-1) (reused LDS), b1 = halo, c1 = own (i,dA)
// One __syncthreads per pair.  Cost loads in a 4-pair static-slot ring.
// ---------------------------------------------------------------------------
__global__ __launch_bounds__(256) void fwd_kernel(const float* __restrict__ gamma_ptr,
                                                  float* __restrict__ d_out)
{
    __shared__ float buf[4][MDIM];     // slot = d & 3

    int b = blockIdx.x;
    int i = threadIdx.x;
    int im1 = (i > 0) ? i - 1 : 0;
    int im2 = (i > 1) ? i - 2 : 0;

    float gv  = fmaxf(fabsf(*gamma_ptr), GAMMA_MIN);
    float ig2 = 1.4426950408889634f / gv;       // log2(e)/gv
    float gl  = gv * 0.6931471805599453f;       // gv*ln(2)

    const float* costb = g_cost + (size_t)b * NDIAG * MDIM;
    float* Rb = g_R + (size_t)b * NDIAG * MDIM;
    float* Sb = g_S + (size_t)b * NDIAG * MDIM;

    // cost prefetch rings: per pair need cost(i,dA), cost(i,dB), cost(i-1,dA)
    float c0reg[UNRP], c1reg[UNRP], chreg[UNRP];
#pragma unroll
    for (int u = 0; u < UNRP; ++u) {
        int dA = 2 * u, dB = dA + 1;
        c0reg[u] = costb[(size_t)dA * MDIM + i];
        c1reg[u] = costb[(size_t)dB * MDIM + i];
        chreg[u] = costb[(size_t)dA * MDIM + im1];
    }

    for (int t = 0; t < 256; t += UNRP) {
#pragma unroll
        for (int u = 0; u < UNRP; ++u) {
            int p  = t + u;
            int dA = 2 * p;
            int dB = dA + 1;
            int j  = dA - i;
            int j1 = j + 1;

            float cvA = c0reg[u];
            float cvB = c1reg[u];
            float cvH = chreg[u];
            // prefetch for pair p + UNRP (8 diagonals ahead)
            {
                int dA2 = dA + 2 * UNRP, dB2 = dA2 + 1;
                if (dA2 < NDIAG) {
                    c0reg[u] = costb[(size_t)dA2 * MDIM + i];
                    chreg[u] = costb[(size_t)dA2 * MDIM + im1];
                }
                if (dB2 < NDIAG)
                    c1reg[u] = costb[(size_t)dB2 * MDIM + i];
            }

            // static smem slots (t multiple of 4 -> 2t = 0 mod 4)
            const int sA  = (2 * u) & 3;        // dA   mod 4
            const int sB  = (2 * u + 1) & 3;    // dB   mod 4
            const int sm1 = (2 * u + 3) & 3;    // dA-1 mod 4
            const int sm2 = (2 * u + 2) & 3;    // dA-2 mod 4

            // raw smem reads (guards applied per-use)
            float r_m1_im1 = buf[sm1][im1];
            float r_m2_im1 = buf[sm2][im1];
            float r_m1_i   = buf[sm1][i];
            float r_m1_im2 = buf[sm1][im2];
            float r_m2_im2 = buf[sm2][im2];

            // ---- cell (i, dA) ----
            float a  = (i > 0 && j > 0) ? r_m2_im1
                                        : ((i == 0 && j == 0) ? 0.0f : INFV);
            float bb = (i > 0) ? r_m1_im1 : INFV;
            float cc = (j > 0) ? r_m1_i   : INFV;
            float SvA = softmin3(a, bb, cc, ig2, gl);
            float RvA = cvA + SvA;

            // ---- halo cell (i-1, dA), jh = j+1 (independent of cell A) ----
            float a_h = (i > 1 && j1 > 0) ? r_m2_im2
                                          : ((i == 1 && j1 == 0) ? 0.0f : INFV);
            float b_h = (i > 1) ? r_m1_im2 : INFV;
            float c_h = (j1 > 0) ? r_m1_im1 : INFV;
            float RvH = cvH + softmin3(a_h, b_h, c_h, ig2, gl);

            // ---- cell (i, dB) from registers ----
            float a1 = (i > 0 && j1 > 0) ? r_m1_im1 : INFV;   // R(dA-1, i-1)
            float b1 = (i > 0) ? RvH : INFV;                  // R(dA,   i-1)
            float c1 = (j1 > 0) ? RvA : INFV;                 // R(dA,   i)
            float SvB = softmin3(a1, b1, c1, ig2, gl);
            float RvB = cvB + SvB;

            bool validA = (j  >= 0) && (j  < NDIM);
            bool validB = (j1 >= 0) && (j1 < NDIM);

            if (validA) {
                buf[sA][i] = RvA;
                Rb[(size_t)dA * MDIM + i] = RvA;
                Sb[(size_t)dA * MDIM + i] = SvA;
                if (dA == NDIAG - 1)
                    d_out[BATCH * MDIM * NDIM + b] = RvA;   // distance (i==255)
            }
            if (validB) {
                buf[sB][i] = RvB;
                Rb[(size_t)dB * MDIM + i] = RvB;
                Sb[(size_t)dB * MDIM + i] = SvB;
            }
            __syncthreads();
        }
    }
}

// ---------------------------------------------------------------------------
// Kernel 4: precompute backward weights per cell (fully parallel).
// Zero for invalid cells/neighbors -> bwd needs no validity logic at all.
// ---------------------------------------------------------------------------
__global__ __launch_bounds__(256) void weights_kernel(const float* __restrict__ gamma_ptr)
{
    int d = blockIdx.x;
    int b = blockIdx.y;
    int i = threadIdx.x;
    int j = d - i;

    float gv = fmaxf(fabsf(*gamma_ptr), GAMMA_MIN);
    float ig = 1.0f / gv;

    const float* Rb = g_R + (size_t)b * NDIAG * MDIM;
    const float* Sb = g_S + (size_t)b * NDIAG * MDIM;

    float4 w = make_float4(0.0f, 0.0f, 0.0f, 0.0f);
    if (j >= 0 && j < NDIM) {
        float rc = Rb[(size_t)d * MDIM + i];
        if (i + 1 < MDIM && j + 1 < NDIM)
            w.x = __expf(clamp50((Sb[(size_t)(d + 2) * MDIM + i + 1] - rc) * ig));
        if (i + 1 < MDIM)
            w.y = __expf(clamp50((Sb[(size_t)(d + 1) * MDIM + i + 1] - rc) * ig));
        if (j + 1 < NDIM)
            w.z = __expf(clamp50((Sb[(size_t)(d + 1) * MDIM + i] - rc) * ig));
    }
    g_W[((size_t)b * NDIAG + d) * MDIM + i] = w;
}

// ---------------------------------------------------------------------------
// Kernel 5: backward soft-DTW wavefront, TWO diagonals per barrier.
// Pair p: dA = 509-2p, dB = dA-1.  After the barrier smem holds dA+1, dA+2.
//   (1) cell (i, dA)        = E[s2][i+1]*wA.x + E[s1][i+1]*wA.y + E[s1][i]*wA.z
//   (2) halo cell (i+1, dA) = E[s2][i+2]*wH.x + E[s1][i+2]*wH.y + E[s1][i+1]*wH.z
//   (3) cell (i, dB)        = E[s1][i+1]*wB.x + halo*wB.y + cellA*wB.z
// E buffers padded (+2 zeros) -> no boundary guards; invalid-cell weights are
// zero -> garbage self-cancels.  One __syncthreads per pair.
// ---------------------------------------------------------------------------
__global__ __launch_bounds__(256) void bwd_kernel()
{
    __shared__ float E[4][MDIM + 2];   // slot = d & 3, padded with zeros

    int b = blockIdx.x;
    int i = threadIdx.x;
    int ip1 = (i < MDIM - 1) ? i + 1 : MDIM - 1;   // clamped halo index

    const float4* Wb = g_W + (size_t)b * NDIAG * MDIM;
    float* Eb = g_E + (size_t)b * NDIAG * MDIM;

    // init: all slots zero (incl. padding), seed diag 510 (slot 2) at i=255
#pragma unroll
    for (int s = 0; s < 4; ++s) {
        E[s][i] = 0.0f;
        if (i < 2) E[s][MDIM + i] = 0.0f;
    }
    if (i == MDIM - 1) E[2][i] = 1.0f;
    Eb[(size_t)(NDIAG - 1) * MDIM + i] = (i == MDIM - 1) ? 1.0f : 0.0f;

    // weight prefetch rings: pairs p=0..3 -> dA = 509,507,505,503 (all >= 1)
    float4 wAreg[UNRP], wBreg[UNRP], wHreg[UNRP];
#pragma unroll
    for (int u = 0; u < UNRP; ++u) {
        int dA = NDIAG - 2 - 2 * u, dB = dA - 1;
        wAreg[u] = Wb[(size_t)dA * MDIM + i];
        wBreg[u] = Wb[(size_t)dB * MDIM + i];
        wHreg[u] = Wb[(size_t)dA * MDIM + ip1];
    }

    __syncthreads();

    for (int t = 0; t < 256; t += UNRP) {
#pragma unroll
        for (int u = 0; u < UNRP; ++u) {
            int p  = t + u;
            int dA = NDIAG - 2 - 2 * p;       // 509, 507, ..., 1, then -1 (pad)
            int dB = dA - 1;

            float4 wA = wAreg[u];
            float4 wB = wBreg[u];
            float4 wH = wHreg[u];
            // prefetch for pair p + UNRP
            {
                int dA2 = dA - 2 * UNRP, dB2 = dA2 - 1;
                if (dA2 >= 0) {
                    wAreg[u] = Wb[(size_t)dA2 * MDIM + i];
                    wHreg[u] = Wb[(size_t)dA2 * MDIM + ip1];
                }
                if (dB2 >= 0)
                    wBreg[u] = Wb[(size_t)dB2 * MDIM + i];
            }

            // static smem slots: dA mod 4 = (509 - 2u) mod 4
            const int sA = (509 - 2 * u) & 3;       // 1,3,1,3
            const int sB = (508 - 2 * u) & 3;       // 0,2,0,2
            const int s1 = (510 - 2 * u) & 3;       // 2,0,2,0
            const int s2 = (511 - 2 * u) & 3;       // 3,1,3,1

            float e2  = E[s2][i + 1];
            float en  = E[s1][i + 1];
            float er  = E[s1][i];
            float e2h = E[s2][i + 2];
            float enh = E[s1][i + 2];

            // cell (i, dA)
            float EvA = fmaf(e2, wA.x, fmaf(en, wA.y, er * wA.z));
            // halo cell (i+1, dA)  (garbage for i=255, cancelled by wB.y=0)
            float EvH = fmaf(e2h, wH.x, fmaf(enh, wH.y, en * wH.z));
            // cell (i, dB)
            float EvB = fmaf(en, wB.x, fmaf(EvH, wB.y, EvA * wB.z));

            E[sA][i] = EvA;
            E[sB][i] = EvB;
            if (dA >= 0) {
                Eb[(size_t)dA * MDIM + i] = EvA;
                Eb[(size_t)dB * MDIM + i] = EvB;
            }
            __syncthreads();
        }
    }
}

// ---------------------------------------------------------------------------
// Kernel 6: diag-major E -> row-major alignment output.  32x32 output tile
// per block.  Cell (i0+r, j0+c) lives at diag r+c, row-slot r: sm[r+c][r].
// Pad to 33 so the read pattern (bank = (2r + lane) mod 32) is conflict-free.
// ---------------------------------------------------------------------------
__global__ __launch_bounds__(256) void transpose_kernel(float* __restrict__ out)
{
    __shared__ float sm[63][33];

    int b  = blockIdx.z;
    int i0 = blockIdx.y * 32;
    int j0 = blockIdx.x * 32;
    int d0 = i0 + j0;

    int lane = threadIdx.x & 31;
    int wy   = threadIdx.x >> 5;       // 0..7

    const float* Eb = g_E + (size_t)b * NDIAG * MDIM;

    // load 63 diagonal segments of 32 consecutive row-slots (coalesced)
    for (int dl = wy; dl < 63; dl += 8)
        sm[dl][lane] = Eb[(size_t)(d0 + dl) * MDIM + i0 + lane];
    __syncthreads();

    float* outb = out + (size_t)b * MDIM * NDIM;
#pragma unroll
    for (int r = wy; r < 32; r += 8)   // row i = i0 + r, col j = j0 + lane
        outb[(size_t)(i0 + r) * NDIM + j0 + lane] = sm[r + lane][r];
}

// ---------------------------------------------------------------------------
// Launch.  Inputs: x [8,256,512] f32, y [8,256,512] f32, gamma [] f32.
// Output: alignment [8,256,256] then distance [8], f32.
// ---------------------------------------------------------------------------
extern "C" void kernel_launch(void* const* d_in, const int* in_sizes, int n_in,
                              void* d_out, int out_size)
{
    const float* x     = (const float*)d_in[0];
    const float* y     = (const float*)d_in[1];
    const float* gamma = (const float*)d_in[2];
    float* out = (float*)d_out;

    norms_kernel<<<512, 256>>>(x, y);
    cost_kernel<<<dim3(NDIM / BN, MDIM / BM, BATCH), dim3(16, 16)>>>(x, y);
    fwd_kernel<<<BATCH, 256>>>(gamma, out);
    weights_kernel<<<dim3(NDIAG, BATCH), 256>>>(gamma);
    bwd_kernel<<<BATCH, 256>>>();
    transpose_kernel<<<dim3(8, 8, BATCH), 256>>>(out);
}